// round 6
// baseline (speedup 1.0000x reference)
#include <cuda_runtime.h>
#include <cstdint>

// Problem constants (from reference)
#define NTOKENS    8192
#define TOPK       2
#define HIDDEN     4096
#define NUM_GROUPS 2
#define M_FULL     (NTOKENS * TOPK)   // 16384
#define NIDX       (NTOKENS * TOPK)   // 16384 index elements

// Device flag: 1 if scatter_index is int64, 0 if int32 (detected at runtime).
__device__ int g_is64;

// ---------------------------------------------------------------------------
// Dtype detection (single block). View the first 16384 int32 words — safe for
// both int32 (64KB buffer, all words) and int64 (128KB, first half).
// If int64: odd words are high halves of values < 16384 -> all zero.
// If int32: odd words are random indices -> OR is nonzero w.p. ~1.
// ---------------------------------------------------------------------------
__global__ void k_detect(const int* __restrict__ idx32) {
    __shared__ int s_or[32];
    int v = 0;
    // 1024 threads, 8 odd-words each: covers odd indices 1,3,...,16383
    #pragma unroll
    for (int r = 0; r < 8; r++) {
        int w = threadIdx.x + r * 1024;          // 0..8191
        v |= idx32[2 * w + 1];
    }
    #pragma unroll
    for (int off = 16; off > 0; off >>= 1)
        v |= __shfl_down_sync(0xFFFFFFFFu, v, off);
    if ((threadIdx.x & 31) == 0) s_or[threadIdx.x >> 5] = v;
    __syncthreads();
    if (threadIdx.x < 32) {
        int t = s_or[threadIdx.x];
        #pragma unroll
        for (int off = 16; off > 0; off >>= 1)
            t |= __shfl_down_sync(0xFFFFFFFFu, t, off);
        if (threadIdx.x == 0) g_is64 = (t == 0) ? 1 : 0;
    }
}

// ---------------------------------------------------------------------------
// Main kernel: out[t, :] = buf[0,i0,:] + buf[0,i1,:] + buf[1,i0,:] + buf[1,i1,:]
//   One 256-thread CTA per token. Each thread: 4 float4 chunks, each chunk
//   summing 4 source rows -> 16 LDG.128 + 4 STG.128 per thread, coalesced.
// ---------------------------------------------------------------------------
__global__ __launch_bounds__(256) void k_gather_sum(
    const float* __restrict__ buf,
    const void*  __restrict__ idx,
    float*       __restrict__ out)
{
    const int t = blockIdx.x;

    int i0, i1;
    if (g_is64) {
        const long long* p = (const long long*)idx;
        i0 = (int)p[(size_t)t * TOPK + 0];
        i1 = (int)p[(size_t)t * TOPK + 1];
    } else {
        const int* p = (const int*)idx;
        i0 = p[t * TOPK + 0];
        i1 = p[t * TOPK + 1];
    }

    const float4* __restrict__ b4 = (const float4*)buf;
    const size_t R = HIDDEN / 4;                     // 1024 float4 per row
    const size_t p00 = (size_t)i0 * R;               // group 0, i0
    const size_t p01 = (size_t)i1 * R;               // group 0, i1
    const size_t p10 = ((size_t)M_FULL + i0) * R;    // group 1, i0
    const size_t p11 = ((size_t)M_FULL + i1) * R;    // group 1, i1

    float4* __restrict__ o4 = (float4*)out + (size_t)t * R;

    #pragma unroll
    for (int c = 0; c < 4; c++) {
        const int jj = threadIdx.x + c * 256;
        float4 a = b4[p00 + jj];
        float4 b = b4[p01 + jj];
        float4 d = b4[p10 + jj];
        float4 e = b4[p11 + jj];
        float4 s;
        s.x = (a.x + b.x) + (d.x + e.x);
        s.y = (a.y + b.y) + (d.y + e.y);
        s.z = (a.z + b.z) + (d.z + e.z);
        s.w = (a.w + b.w) + (d.w + e.w);
        o4[jj] = s;
    }
}

// ---------------------------------------------------------------------------
// Launch contract
//   d_in[0]: gemm_buffer   float32 [NUM_GROUPS, M_FULL, HIDDEN]
//   d_in[1]: scatter_index int32 or int64 [NTOKENS, TOPK] (device-detected)
//   d_out  : float32 [NTOKENS, HIDDEN]
// ---------------------------------------------------------------------------
extern "C" void kernel_launch(void* const* d_in, const int* in_sizes, int n_in,
                              void* d_out, int out_size) {
    const float* buf = (const float*)d_in[0];
    const void*  idx = d_in[1];
    float*       out = (float*)d_out;

    k_detect<<<1, 1024>>>((const int*)idx);
    k_gather_sum<<<NTOKENS, 256>>>(buf, idx, out);
}